// round 12
// baseline (speedup 1.0000x reference)
#include <cuda_runtime.h>
#include <cuda_bf16.h>
#include <stdint.h>

// ----------------------------------------------------------------------------
// VQExpert, two-phase: (1) bf16 hi-only HMMA GEMM -> approximate distances,
// per-row per-16-code-group best keys; (2) refine: exact fp32 distance for
// all codes in groups within DELTA of the row's best approx distance.
// R12: refine parallelized -- one block per row, 16 lanes per candidate code,
// 4-way ILP dot (was: 1 warp/row, 2 lanes/code, serial chain -> 721us).
// ----------------------------------------------------------------------------

#define KDIM 512
#define MDIM 32768
#define NDIM 8192
#define BM 128
#define BN 128
#define BK 32
#define STAGES 3
#define NKT (KDIM / BK)        // 16
#define NGRP (NDIM / 16)       // 512 groups of 16 codes
#define DELTA 0.10f
// stage regions: Ah 8KB | Bh 8KB ; stage = 16KB
#define R_BH 8192
#define STG  16384
#define SMEM_DYN (STAGES * STG)   // 49152

__device__ __align__(16) __nv_bfloat16 g_Ah[(size_t)MDIM * KDIM];
__device__ __align__(16) __nv_bfloat16 g_Bh[(size_t)NDIM * KDIM];
__device__ float g_zsq[MDIM];
__device__ float g_esq[NDIM];
__device__ unsigned long long g_gb[(size_t)MDIM * NGRP];  // per-row group keys
__device__ unsigned int g_bestidx[MDIM];
__device__ float g_partials[MDIM];

// ------------------------------------------------------------ PTX helpers
__device__ __forceinline__ uint32_t smem_u32(const void* p) {
    uint32_t a;
    asm("{ .reg .u64 t; cvta.to.shared.u64 t, %1; cvt.u32.u64 %0, t; }"
        : "=r"(a) : "l"(p));
    return a;
}
__device__ __forceinline__ void cp16(uint32_t dst, const void* src) {
    asm volatile("cp.async.cg.shared.global [%0], [%1], 16;"
                 :: "r"(dst), "l"(src) : "memory");
}
__device__ __forceinline__ void ldsm4(uint32_t* r, uint32_t addr) {
    asm volatile("ldmatrix.sync.aligned.m8n8.x4.shared.b16 {%0,%1,%2,%3}, [%4];"
                 : "=r"(r[0]), "=r"(r[1]), "=r"(r[2]), "=r"(r[3]) : "r"(addr));
}
__device__ __forceinline__ void mma16816(float* c, const uint32_t* a,
                                         uint32_t b0, uint32_t b1) {
    asm volatile(
        "mma.sync.aligned.m16n8k16.row.col.f32.bf16.bf16.f32 "
        "{%0,%1,%2,%3}, {%4,%5,%6,%7}, {%8,%9}, {%0,%1,%2,%3};"
        : "+f"(c[0]), "+f"(c[1]), "+f"(c[2]), "+f"(c[3])
        : "r"(a[0]), "r"(a[1]), "r"(a[2]), "r"(a[3]), "r"(b0), "r"(b1));
}
__device__ __forceinline__ uint32_t swz64(uint32_t off) {
    return off ^ ((off >> 3) & 0x30);
}
__device__ __forceinline__ uint32_t packbf2(__nv_bfloat16 a, __nv_bfloat16 b) {
    __nv_bfloat162 t; t.x = a; t.y = b;
    return *(uint32_t*)&t;
}
__device__ __forceinline__ unsigned enc(float f) {
    unsigned u = __float_as_uint(f);
    return (u & 0x80000000u) ? ~u : (u | 0x80000000u);
}
__device__ __forceinline__ float dec(unsigned x) {
    return (x & 0x80000000u) ? __uint_as_float(x & 0x7FFFFFFFu)
                             : __uint_as_float(~x);
}

// ------------------------------------------------------------ split + sumsq
__global__ void splitA_kernel(const float* __restrict__ z)
{
    int i = blockIdx.x * 256 + threadIdx.x;     // over MDIM*128
    int m = i >> 7, kc = (i & 127) << 2;
    float4 v = *(const float4*)(z + (size_t)m * KDIM + kc);
    uint2 H;
    H.x = packbf2(__float2bfloat16(v.x), __float2bfloat16(v.y));
    H.y = packbf2(__float2bfloat16(v.z), __float2bfloat16(v.w));
    *(uint2*)(g_Ah + (size_t)m * KDIM + kc) = H;
    float s = v.x * v.x + v.y * v.y + v.z * v.z + v.w * v.w;
    #pragma unroll
    for (int o = 16; o; o >>= 1) s += __shfl_down_sync(0xffffffffu, s, o);
    __shared__ float ws[8];
    int t = threadIdx.x;
    if ((t & 31) == 0) ws[t >> 5] = s;
    __syncthreads();
    if (t == 0)   g_zsq[m] = ws[0] + ws[1] + ws[2] + ws[3];
    if (t == 128) g_zsq[m] = ws[4] + ws[5] + ws[6] + ws[7];
}
__global__ void splitB_kernel(const float* __restrict__ cb)
{
    int i = blockIdx.x * 256 + threadIdx.x;     // over NDIM*128
    int n = i >> 7, kc = (i & 127) << 2;
    float4 v = *(const float4*)(cb + (size_t)n * KDIM + kc);
    uint2 H;
    H.x = packbf2(__float2bfloat16(v.x), __float2bfloat16(v.y));
    H.y = packbf2(__float2bfloat16(v.z), __float2bfloat16(v.w));
    *(uint2*)(g_Bh + (size_t)n * KDIM + kc) = H;
    float s = v.x * v.x + v.y * v.y + v.z * v.z + v.w * v.w;
    #pragma unroll
    for (int o = 16; o; o >>= 1) s += __shfl_down_sync(0xffffffffu, s, o);
    __shared__ float ws[8];
    int t = threadIdx.x;
    if ((t & 31) == 0) ws[t >> 5] = s;
    __syncthreads();
    if (t == 0)   g_esq[n] = ws[0] + ws[1] + ws[2] + ws[3];
    if (t == 128) g_esq[n] = ws[4] + ws[5] + ws[6] + ws[7];
}

// ------------------------------------------------------------ hi-only GEMM
__global__ __launch_bounds__(256, 2)
void gemm_hmma_kernel()
{
    extern __shared__ char smem[];
    __shared__ float s_esq[BN];
    const uint32_t smb = smem_u32(smem);
    const int tid = threadIdx.x;
    const int lane = tid & 31, warp = tid >> 5;
    const int m0 = blockIdx.y * BM;
    const int n0 = blockIdx.x * BN;

    uint32_t swo[2];
    const __nv_bfloat16 *sAh[2], *sBh[2];
    #pragma unroll
    for (int r = 0; r < 2; r++) {
        int q = tid + r * 256, row = q >> 2, c = q & 3;
        swo[r] = swz64(row * 64 + c * 16);
        sAh[r] = g_Ah + (size_t)(m0 + row) * KDIM + c * 8;
        sBh[r] = g_Bh + (size_t)(n0 + row) * KDIM + c * 8;
    }

    #pragma unroll
    for (int s = 0; s < STAGES - 1; s++) {
        uint32_t bo = (uint32_t)s * STG;
        int k0 = s * BK;
        #pragma unroll
        for (int r = 0; r < 2; r++) {
            cp16(smb + bo + swo[r],        sAh[r] + k0);
            cp16(smb + bo + R_BH + swo[r], sBh[r] + k0);
        }
        asm volatile("cp.async.commit_group;" ::: "memory");
    }

    if (tid < BN) s_esq[tid] = g_esq[n0 + tid];

    float acc[4][4][4];
    #pragma unroll
    for (int i = 0; i < 4; i++)
        #pragma unroll
        for (int j = 0; j < 4; j++)
            #pragma unroll
            for (int q = 0; q < 4; q++) acc[i][j][q] = 0.f;

    const int wm = (warp & 1) * 64;
    const int wn = (warp >> 1) * 32;
    const uint32_t a_row = wm + (lane & 15);
    const uint32_t b_row = wn + (lane & 15);
    const uint32_t kchunk = (lane >> 4);

    for (int kt = 0; kt < NKT; kt++) {
        asm volatile("cp.async.wait_group %0;" :: "n"(STAGES - 2));
        __syncthreads();

        int pf = kt + STAGES - 1;
        if (pf < NKT) {
            uint32_t bo = (uint32_t)(pf % STAGES) * STG;
            int k0 = pf * BK;
            #pragma unroll
            for (int r = 0; r < 2; r++) {
                cp16(smb + bo + swo[r],        sAh[r] + k0);
                cp16(smb + bo + R_BH + swo[r], sBh[r] + k0);
            }
        }
        asm volatile("cp.async.commit_group;" ::: "memory");

        const uint32_t sA = smb + (uint32_t)(kt % STAGES) * STG;
        #pragma unroll
        for (int kk = 0; kk < 2; kk++) {
            const uint32_t kof = (kk * 2 + kchunk) * 16;
            uint32_t aH[4][4], b[2][4];
            #pragma unroll
            for (int i = 0; i < 4; i++)
                ldsm4(aH[i], sA + swz64((a_row + i * 16) * 64 + kof));
            #pragma unroll
            for (int p = 0; p < 2; p++)
                ldsm4(b[p], sA + R_BH + swz64((b_row + p * 16) * 64 + kof));
            #pragma unroll
            for (int i = 0; i < 4; i++)
                #pragma unroll
                for (int j = 0; j < 4; j++) {
                    int p = j >> 1, h = j & 1;
                    mma16816(acc[i][j], aH[i], b[p][h], b[p][h + 2]);
                }
        }
    }

    // ---- epilogue: approx dist' = esq - 2*acc; per-16-code group keys.
    const int r0 = lane >> 2;
    const int gbase = (n0 >> 4) + (wn >> 4);
    #pragma unroll
    for (int i = 0; i < 4; i++) {
        int rowa = wm + i * 16 + r0;
        #pragma unroll
        for (int jp = 0; jp < 2; jp++) {
            unsigned long long bk0 = 0xFFFFFFFFFFFFFFFFull;
            unsigned long long bk1 = 0xFFFFFFFFFFFFFFFFull;
            #pragma unroll
            for (int jj = 0; jj < 2; jj++) {
                int j = jp * 2 + jj;
                int ncol = wn + j * 8 + 2 * (lane & 3);
                float e0 = s_esq[ncol], e1 = s_esq[ncol + 1];
                unsigned gn0 = (unsigned)(n0 + ncol), gn1 = gn0 + 1;
                float d; unsigned long long k;
                d = e0 - 2.0f * acc[i][j][0];
                k = ((unsigned long long)enc(d) << 32) | gn0; if (k < bk0) bk0 = k;
                d = e1 - 2.0f * acc[i][j][1];
                k = ((unsigned long long)enc(d) << 32) | gn1; if (k < bk0) bk0 = k;
                d = e0 - 2.0f * acc[i][j][2];
                k = ((unsigned long long)enc(d) << 32) | gn0; if (k < bk1) bk1 = k;
                d = e1 - 2.0f * acc[i][j][3];
                k = ((unsigned long long)enc(d) << 32) | gn1; if (k < bk1) bk1 = k;
            }
            #pragma unroll
            for (int o = 1; o <= 2; o <<= 1) {
                unsigned long long t0 = __shfl_xor_sync(0xffffffffu, bk0, o);
                unsigned long long t1 = __shfl_xor_sync(0xffffffffu, bk1, o);
                if (t0 < bk0) bk0 = t0;
                if (t1 < bk1) bk1 = t1;
            }
            if ((lane & 3) == 0) {
                g_gb[(size_t)(m0 + rowa) * NGRP + gbase + jp] = bk0;
                g_gb[(size_t)(m0 + rowa + 8) * NGRP + gbase + jp] = bk1;
            }
        }
    }
}

// ------------------------------------------------------------ refine (exact)
// One block (256 threads) per row. 16 lanes per candidate code.
__global__ __launch_bounds__(256)
void refine_kernel(const float* __restrict__ z, const float* __restrict__ cb)
{
    const int row = blockIdx.x;
    const int tid = threadIdx.x;
    const int lane = tid & 31, wid = tid >> 5;
    const unsigned long long* keys = g_gb + (size_t)row * NGRP;

    __shared__ unsigned long long s_min;
    __shared__ unsigned long long s_best;
    __shared__ int s_cnt;
    __shared__ short s_list[64];

    if (tid == 0) {
        s_min = 0xFFFFFFFFFFFFFFFFull;
        s_best = 0xFFFFFFFFFFFFFFFFull;
        s_cnt = 0;
    }
    __syncthreads();

    // phase 1: row-min key (each thread 2 keys)
    unsigned long long kmin = keys[tid];
    {
        unsigned long long k2 = keys[tid + 256];
        if (k2 < kmin) kmin = k2;
    }
    #pragma unroll
    for (int o = 16; o; o >>= 1) {
        unsigned long long t = __shfl_xor_sync(0xffffffffu, kmin, o);
        if (t < kmin) kmin = t;
    }
    if (lane == 0) atomicMin(&s_min, kmin);
    __syncthreads();
    float th = dec((unsigned)(s_min >> 32)) + DELTA;

    // phase 2: flag groups within threshold
    #pragma unroll
    for (int r = 0; r < 2; r++) {
        int g = tid + r * 256;
        if (dec((unsigned)(keys[g] >> 32)) <= th) {
            int p = atomicAdd(&s_cnt, 1);
            if (p < 64) s_list[p] = (short)g;
        }
    }
    __syncthreads();
    int nf = s_cnt < 64 ? s_cnt : 64;

    // phase 3: exact fp32 distances; 8 warps x 2 codes = 16 codes per group,
    // 16 lanes per code, 4-way ILP dot.
    float zs = g_zsq[row];
    const int sub = lane >> 4;      // which code within the warp pair
    const int l16 = lane & 15;      // lane within code
    const float4* zr = (const float4*)(z + (size_t)row * KDIM) + l16 * 8;
    unsigned long long best = 0xFFFFFFFFFFFFFFFFull;
    for (int f = 0; f < nf; f++) {
        int code = (int)s_list[f] * 16 + wid * 2 + sub;
        const float4* cr = (const float4*)(cb + (size_t)code * KDIM) + l16 * 8;
        float d0 = 0.f, d1 = 0.f, d2 = 0.f, d3 = 0.f;
        #pragma unroll
        for (int k = 0; k < 8; k += 4) {
            float4 a0 = zr[k],     b0 = cr[k];
            float4 a1 = zr[k + 1], b1 = cr[k + 1];
            float4 a2 = zr[k + 2], b2 = cr[k + 2];
            float4 a3 = zr[k + 3], b3 = cr[k + 3];
            d0 += a0.x * b0.x + a0.y * b0.y + a0.z * b0.z + a0.w * b0.w;
            d1 += a1.x * b1.x + a1.y * b1.y + a1.z * b1.z + a1.w * b1.w;
            d2 += a2.x * b2.x + a2.y * b2.y + a2.z * b2.z + a2.w * b2.w;
            d3 += a3.x * b3.x + a3.y * b3.y + a3.z * b3.z + a3.w * b3.w;
        }
        float dot = (d0 + d1) + (d2 + d3);
        #pragma unroll
        for (int o = 1; o <= 8; o <<= 1)
            dot += __shfl_xor_sync(0xffffffffu, dot, o);
        float d = (zs + g_esq[code]) - 2.0f * dot;
        unsigned long long key =
            ((unsigned long long)enc(d) << 32) | (unsigned)code;
        if (key < best) best = key;
    }
    // phase 4: block reduce
    #pragma unroll
    for (int o = 16; o; o >>= 1) {
        unsigned long long t = __shfl_xor_sync(0xffffffffu, best, o);
        if (t < best) best = t;
    }
    if (lane == 0) atomicMin(&s_best, best);
    __syncthreads();
    if (tid == 0) g_bestidx[row] = (unsigned)s_best;
}

// ------------------------------------------------------------ gather + loss
__global__ void gather_loss_kernel(const float* __restrict__ z,
                                   const float* __restrict__ cb,
                                   float* __restrict__ out_q,
                                   float* __restrict__ out_idx)
{
    int m = blockIdx.x;
    unsigned int idx = g_bestidx[m];
    const float4* zr = (const float4*)(z + (size_t)m * KDIM);
    const float4* cr = (const float4*)(cb + (size_t)idx * KDIM);
    float4* qr = (float4*)(out_q + (size_t)m * KDIM);
    float4 ze = zr[threadIdx.x];
    float4 cq = cr[threadIdx.x];
    float d0 = cq.x - ze.x, d1 = cq.y - ze.y, d2 = cq.z - ze.z, d3 = cq.w - ze.w;
    float4 o;
    o.x = ze.x + d0; o.y = ze.y + d1; o.z = ze.z + d2; o.w = ze.w + d3;
    qr[threadIdx.x] = o;
    float s = d0 * d0 + d1 * d1 + d2 * d2 + d3 * d3;
    #pragma unroll
    for (int off = 16; off; off >>= 1) s += __shfl_down_sync(0xffffffffu, s, off);
    __shared__ float ws[4];
    if ((threadIdx.x & 31) == 0) ws[threadIdx.x >> 5] = s;
    __syncthreads();
    if (threadIdx.x == 0) {
        g_partials[m] = ws[0] + ws[1] + ws[2] + ws[3];
        out_idx[m] = (float)idx;
    }
}

__global__ void loss_kernel(float* __restrict__ out_loss, int M, int K)
{
    __shared__ float sm[1024];
    float s = 0.f;
    for (int i = threadIdx.x; i < M; i += 1024) s += g_partials[i];
    sm[threadIdx.x] = s;
    __syncthreads();
    for (int o = 512; o; o >>= 1) {
        if (threadIdx.x < o) sm[threadIdx.x] += sm[threadIdx.x + o];
        __syncthreads();
    }
    if (threadIdx.x == 0) {
        float mean = sm[0] / ((float)M * (float)K);
        out_loss[0] = (mean + 0.25f * mean) / (float)K;
    }
}

// ------------------------------------------------------------ launch
extern "C" void kernel_launch(void* const* d_in, const int* in_sizes, int n_in,
                              void* d_out, int out_size)
{
    const float* z  = (const float*)d_in[0];
    const float* cb = (const float*)d_in[1];
    const int M = in_sizes[0] / KDIM;   // 32768
    const int N = in_sizes[1] / KDIM;   // 8192

    float* out      = (float*)d_out;
    float* out_q    = out;
    float* out_idx  = out + (size_t)M * KDIM;
    float* out_loss = out_idx + M;

    static int attr_done = 0;
    if (!attr_done) {
        cudaFuncSetAttribute(gemm_hmma_kernel,
                             cudaFuncAttributeMaxDynamicSharedMemorySize,
                             SMEM_DYN);
        attr_done = 1;
    }

    splitA_kernel<<<M * 128 / 256, 256>>>(z);
    splitB_kernel<<<N * 128 / 256, 256>>>(cb);

    dim3 grid(N / BN, M / BM);
    gemm_hmma_kernel<<<grid, 256, SMEM_DYN>>>();

    refine_kernel<<<M, 256>>>(z, cb);
    gather_loss_kernel<<<M, 128>>>(z, cb, out_q, out_idx);
    loss_kernel<<<1, 1024>>>(out_loss, M, KDIM);
}

// round 13
// speedup vs baseline: 2.1358x; 2.1358x over previous
#include <cuda_runtime.h>
#include <cuda_bf16.h>
#include <stdint.h>

// ----------------------------------------------------------------------------
// VQExpert, two-phase: (1) bf16 hi-only HMMA GEMM -> approximate distances,
// per-row per-16-code-group best keys; (2) refine: exact fp32 distance for
// all codes in groups within DELTA of the row's best approx distance.
// R13: refine loads coalesced (z row staged in smem; codebook read with
// k*16+l16 transposed indexing -> contiguous 256B per step). R12's refine
// was L1-wavefront bound (92% L1, 128B lane stride).
// ----------------------------------------------------------------------------

#define KDIM 512
#define MDIM 32768
#define NDIM 8192
#define BM 128
#define BN 128
#define BK 32
#define STAGES 3
#define NKT (KDIM / BK)        // 16
#define NGRP (NDIM / 16)       // 512 groups of 16 codes
#define DELTA 0.10f
// stage regions: Ah 8KB | Bh 8KB ; stage = 16KB
#define R_BH 8192
#define STG  16384
#define SMEM_DYN (STAGES * STG)   // 49152

__device__ __align__(16) __nv_bfloat16 g_Ah[(size_t)MDIM * KDIM];
__device__ __align__(16) __nv_bfloat16 g_Bh[(size_t)NDIM * KDIM];
__device__ float g_zsq[MDIM];
__device__ float g_esq[NDIM];
__device__ unsigned long long g_gb[(size_t)MDIM * NGRP];  // per-row group keys
__device__ unsigned int g_bestidx[MDIM];
__device__ float g_partials[MDIM];

// ------------------------------------------------------------ PTX helpers
__device__ __forceinline__ uint32_t smem_u32(const void* p) {
    uint32_t a;
    asm("{ .reg .u64 t; cvta.to.shared.u64 t, %1; cvt.u32.u64 %0, t; }"
        : "=r"(a) : "l"(p));
    return a;
}
__device__ __forceinline__ void cp16(uint32_t dst, const void* src) {
    asm volatile("cp.async.cg.shared.global [%0], [%1], 16;"
                 :: "r"(dst), "l"(src) : "memory");
}
__device__ __forceinline__ void ldsm4(uint32_t* r, uint32_t addr) {
    asm volatile("ldmatrix.sync.aligned.m8n8.x4.shared.b16 {%0,%1,%2,%3}, [%4];"
                 : "=r"(r[0]), "=r"(r[1]), "=r"(r[2]), "=r"(r[3]) : "r"(addr));
}
__device__ __forceinline__ void mma16816(float* c, const uint32_t* a,
                                         uint32_t b0, uint32_t b1) {
    asm volatile(
        "mma.sync.aligned.m16n8k16.row.col.f32.bf16.bf16.f32 "
        "{%0,%1,%2,%3}, {%4,%5,%6,%7}, {%8,%9}, {%0,%1,%2,%3};"
        : "+f"(c[0]), "+f"(c[1]), "+f"(c[2]), "+f"(c[3])
        : "r"(a[0]), "r"(a[1]), "r"(a[2]), "r"(a[3]), "r"(b0), "r"(b1));
}
__device__ __forceinline__ uint32_t swz64(uint32_t off) {
    return off ^ ((off >> 3) & 0x30);
}
__device__ __forceinline__ uint32_t packbf2(__nv_bfloat16 a, __nv_bfloat16 b) {
    __nv_bfloat162 t; t.x = a; t.y = b;
    return *(uint32_t*)&t;
}
__device__ __forceinline__ unsigned enc(float f) {
    unsigned u = __float_as_uint(f);
    return (u & 0x80000000u) ? ~u : (u | 0x80000000u);
}
__device__ __forceinline__ float dec(unsigned x) {
    return (x & 0x80000000u) ? __uint_as_float(x & 0x7FFFFFFFu)
                             : __uint_as_float(~x);
}

// ------------------------------------------------------------ split + sumsq
__global__ void splitA_kernel(const float* __restrict__ z)
{
    int i = blockIdx.x * 256 + threadIdx.x;     // over MDIM*128
    int m = i >> 7, kc = (i & 127) << 2;
    float4 v = *(const float4*)(z + (size_t)m * KDIM + kc);
    uint2 H;
    H.x = packbf2(__float2bfloat16(v.x), __float2bfloat16(v.y));
    H.y = packbf2(__float2bfloat16(v.z), __float2bfloat16(v.w));
    *(uint2*)(g_Ah + (size_t)m * KDIM + kc) = H;
    float s = v.x * v.x + v.y * v.y + v.z * v.z + v.w * v.w;
    #pragma unroll
    for (int o = 16; o; o >>= 1) s += __shfl_down_sync(0xffffffffu, s, o);
    __shared__ float ws[8];
    int t = threadIdx.x;
    if ((t & 31) == 0) ws[t >> 5] = s;
    __syncthreads();
    if (t == 0)   g_zsq[m] = ws[0] + ws[1] + ws[2] + ws[3];
    if (t == 128) g_zsq[m] = ws[4] + ws[5] + ws[6] + ws[7];
}
__global__ void splitB_kernel(const float* __restrict__ cb)
{
    int i = blockIdx.x * 256 + threadIdx.x;     // over NDIM*128
    int n = i >> 7, kc = (i & 127) << 2;
    float4 v = *(const float4*)(cb + (size_t)n * KDIM + kc);
    uint2 H;
    H.x = packbf2(__float2bfloat16(v.x), __float2bfloat16(v.y));
    H.y = packbf2(__float2bfloat16(v.z), __float2bfloat16(v.w));
    *(uint2*)(g_Bh + (size_t)n * KDIM + kc) = H;
    float s = v.x * v.x + v.y * v.y + v.z * v.z + v.w * v.w;
    #pragma unroll
    for (int o = 16; o; o >>= 1) s += __shfl_down_sync(0xffffffffu, s, o);
    __shared__ float ws[8];
    int t = threadIdx.x;
    if ((t & 31) == 0) ws[t >> 5] = s;
    __syncthreads();
    if (t == 0)   g_esq[n] = ws[0] + ws[1] + ws[2] + ws[3];
    if (t == 128) g_esq[n] = ws[4] + ws[5] + ws[6] + ws[7];
}

// ------------------------------------------------------------ hi-only GEMM
__global__ __launch_bounds__(256, 2)
void gemm_hmma_kernel()
{
    extern __shared__ char smem[];
    __shared__ float s_esq[BN];
    const uint32_t smb = smem_u32(smem);
    const int tid = threadIdx.x;
    const int lane = tid & 31, warp = tid >> 5;
    const int m0 = blockIdx.y * BM;
    const int n0 = blockIdx.x * BN;

    uint32_t swo[2];
    const __nv_bfloat16 *sAh[2], *sBh[2];
    #pragma unroll
    for (int r = 0; r < 2; r++) {
        int q = tid + r * 256, row = q >> 2, c = q & 3;
        swo[r] = swz64(row * 64 + c * 16);
        sAh[r] = g_Ah + (size_t)(m0 + row) * KDIM + c * 8;
        sBh[r] = g_Bh + (size_t)(n0 + row) * KDIM + c * 8;
    }

    #pragma unroll
    for (int s = 0; s < STAGES - 1; s++) {
        uint32_t bo = (uint32_t)s * STG;
        int k0 = s * BK;
        #pragma unroll
        for (int r = 0; r < 2; r++) {
            cp16(smb + bo + swo[r],        sAh[r] + k0);
            cp16(smb + bo + R_BH + swo[r], sBh[r] + k0);
        }
        asm volatile("cp.async.commit_group;" ::: "memory");
    }

    if (tid < BN) s_esq[tid] = g_esq[n0 + tid];

    float acc[4][4][4];
    #pragma unroll
    for (int i = 0; i < 4; i++)
        #pragma unroll
        for (int j = 0; j < 4; j++)
            #pragma unroll
            for (int q = 0; q < 4; q++) acc[i][j][q] = 0.f;

    const int wm = (warp & 1) * 64;
    const int wn = (warp >> 1) * 32;
    const uint32_t a_row = wm + (lane & 15);
    const uint32_t b_row = wn + (lane & 15);
    const uint32_t kchunk = (lane >> 4);

    for (int kt = 0; kt < NKT; kt++) {
        asm volatile("cp.async.wait_group %0;" :: "n"(STAGES - 2));
        __syncthreads();

        int pf = kt + STAGES - 1;
        if (pf < NKT) {
            uint32_t bo = (uint32_t)(pf % STAGES) * STG;
            int k0 = pf * BK;
            #pragma unroll
            for (int r = 0; r < 2; r++) {
                cp16(smb + bo + swo[r],        sAh[r] + k0);
                cp16(smb + bo + R_BH + swo[r], sBh[r] + k0);
            }
        }
        asm volatile("cp.async.commit_group;" ::: "memory");

        const uint32_t sA = smb + (uint32_t)(kt % STAGES) * STG;
        #pragma unroll
        for (int kk = 0; kk < 2; kk++) {
            const uint32_t kof = (kk * 2 + kchunk) * 16;
            uint32_t aH[4][4], b[2][4];
            #pragma unroll
            for (int i = 0; i < 4; i++)
                ldsm4(aH[i], sA + swz64((a_row + i * 16) * 64 + kof));
            #pragma unroll
            for (int p = 0; p < 2; p++)
                ldsm4(b[p], sA + R_BH + swz64((b_row + p * 16) * 64 + kof));
            #pragma unroll
            for (int i = 0; i < 4; i++)
                #pragma unroll
                for (int j = 0; j < 4; j++) {
                    int p = j >> 1, h = j & 1;
                    mma16816(acc[i][j], aH[i], b[p][h], b[p][h + 2]);
                }
        }
    }

    // ---- epilogue: approx dist' = esq - 2*acc; per-16-code group keys.
    const int r0 = lane >> 2;
    const int gbase = (n0 >> 4) + (wn >> 4);
    #pragma unroll
    for (int i = 0; i < 4; i++) {
        int rowa = wm + i * 16 + r0;
        #pragma unroll
        for (int jp = 0; jp < 2; jp++) {
            unsigned long long bk0 = 0xFFFFFFFFFFFFFFFFull;
            unsigned long long bk1 = 0xFFFFFFFFFFFFFFFFull;
            #pragma unroll
            for (int jj = 0; jj < 2; jj++) {
                int j = jp * 2 + jj;
                int ncol = wn + j * 8 + 2 * (lane & 3);
                float e0 = s_esq[ncol], e1 = s_esq[ncol + 1];
                unsigned gn0 = (unsigned)(n0 + ncol), gn1 = gn0 + 1;
                float d; unsigned long long k;
                d = e0 - 2.0f * acc[i][j][0];
                k = ((unsigned long long)enc(d) << 32) | gn0; if (k < bk0) bk0 = k;
                d = e1 - 2.0f * acc[i][j][1];
                k = ((unsigned long long)enc(d) << 32) | gn1; if (k < bk0) bk0 = k;
                d = e0 - 2.0f * acc[i][j][2];
                k = ((unsigned long long)enc(d) << 32) | gn0; if (k < bk1) bk1 = k;
                d = e1 - 2.0f * acc[i][j][3];
                k = ((unsigned long long)enc(d) << 32) | gn1; if (k < bk1) bk1 = k;
            }
            #pragma unroll
            for (int o = 1; o <= 2; o <<= 1) {
                unsigned long long t0 = __shfl_xor_sync(0xffffffffu, bk0, o);
                unsigned long long t1 = __shfl_xor_sync(0xffffffffu, bk1, o);
                if (t0 < bk0) bk0 = t0;
                if (t1 < bk1) bk1 = t1;
            }
            if ((lane & 3) == 0) {
                g_gb[(size_t)(m0 + rowa) * NGRP + gbase + jp] = bk0;
                g_gb[(size_t)(m0 + rowa + 8) * NGRP + gbase + jp] = bk1;
            }
        }
    }
}

// ------------------------------------------------------------ refine (exact)
// One block (256 threads) per row; 16 lanes per candidate code.
// z row staged in smem; codebook read with transposed (k*16+l16) indexing
// so each k-step is a contiguous 256B span per code.
__global__ __launch_bounds__(256)
void refine_kernel(const float* __restrict__ z, const float* __restrict__ cb)
{
    const int row = blockIdx.x;
    const int tid = threadIdx.x;
    const int lane = tid & 31, wid = tid >> 5;
    const unsigned long long* keys = g_gb + (size_t)row * NGRP;

    __shared__ unsigned long long s_min;
    __shared__ unsigned long long s_best;
    __shared__ int s_cnt;
    __shared__ short s_list[64];
    __shared__ float4 s_z[128];   // the 2KB z row

    if (tid == 0) {
        s_min = 0xFFFFFFFFFFFFFFFFull;
        s_best = 0xFFFFFFFFFFFFFFFFull;
        s_cnt = 0;
    }
    if (tid < 128)
        s_z[tid] = ((const float4*)(z + (size_t)row * KDIM))[tid];
    __syncthreads();

    // phase 1: row-min key (each thread 2 keys)
    unsigned long long kmin = keys[tid];
    {
        unsigned long long k2 = keys[tid + 256];
        if (k2 < kmin) kmin = k2;
    }
    #pragma unroll
    for (int o = 16; o; o >>= 1) {
        unsigned long long t = __shfl_xor_sync(0xffffffffu, kmin, o);
        if (t < kmin) kmin = t;
    }
    if (lane == 0) atomicMin(&s_min, kmin);
    __syncthreads();
    float th = dec((unsigned)(s_min >> 32)) + DELTA;

    // phase 2: flag groups within threshold
    #pragma unroll
    for (int r = 0; r < 2; r++) {
        int g = tid + r * 256;
        if (dec((unsigned)(keys[g] >> 32)) <= th) {
            int p = atomicAdd(&s_cnt, 1);
            if (p < 64) s_list[p] = (short)g;
        }
    }
    __syncthreads();
    int nf = s_cnt < 64 ? s_cnt : 64;

    // phase 3: exact fp32 distances; 8 warps x 2 codes = 16 codes per group,
    // 16 lanes per code, coalesced loads (k*16 + l16), 4-way ILP.
    float zs = g_zsq[row];
    const int sub = lane >> 4;
    const int l16 = lane & 15;
    unsigned long long best = 0xFFFFFFFFFFFFFFFFull;
    for (int f = 0; f < nf; f++) {
        int code = (int)s_list[f] * 16 + wid * 2 + sub;
        const float4* cr = (const float4*)(cb + (size_t)code * KDIM);
        float d0 = 0.f, d1 = 0.f, d2 = 0.f, d3 = 0.f;
        #pragma unroll
        for (int q = 0; q < 2; q++) {
            int i0 = (q * 4 + 0) * 16 + l16;
            int i1 = (q * 4 + 1) * 16 + l16;
            int i2 = (q * 4 + 2) * 16 + l16;
            int i3 = (q * 4 + 3) * 16 + l16;
            float4 a0 = s_z[i0], b0 = cr[i0];
            float4 a1 = s_z[i1], b1 = cr[i1];
            float4 a2 = s_z[i2], b2 = cr[i2];
            float4 a3 = s_z[i3], b3 = cr[i3];
            d0 += a0.x * b0.x + a0.y * b0.y + a0.z * b0.z + a0.w * b0.w;
            d1 += a1.x * b1.x + a1.y * b1.y + a1.z * b1.z + a1.w * b1.w;
            d2 += a2.x * b2.x + a2.y * b2.y + a2.z * b2.z + a2.w * b2.w;
            d3 += a3.x * b3.x + a3.y * b3.y + a3.z * b3.z + a3.w * b3.w;
        }
        float dot = (d0 + d1) + (d2 + d3);
        #pragma unroll
        for (int o = 1; o <= 8; o <<= 1)
            dot += __shfl_xor_sync(0xffffffffu, dot, o);
        float d = (zs + g_esq[code]) - 2.0f * dot;
        unsigned long long key =
            ((unsigned long long)enc(d) << 32) | (unsigned)code;
        if (key < best) best = key;
    }
    // phase 4: block reduce
    #pragma unroll
    for (int o = 16; o; o >>= 1) {
        unsigned long long t = __shfl_xor_sync(0xffffffffu, best, o);
        if (t < best) best = t;
    }
    if (lane == 0) atomicMin(&s_best, best);
    __syncthreads();
    if (tid == 0) g_bestidx[row] = (unsigned)s_best;
}

// ------------------------------------------------------------ gather + loss
__global__ void gather_loss_kernel(const float* __restrict__ z,
                                   const float* __restrict__ cb,
                                   float* __restrict__ out_q,
                                   float* __restrict__ out_idx)
{
    int m = blockIdx.x;
    unsigned int idx = g_bestidx[m];
    const float4* zr = (const float4*)(z + (size_t)m * KDIM);
    const float4* cr = (const float4*)(cb + (size_t)idx * KDIM);
    float4* qr = (float4*)(out_q + (size_t)m * KDIM);
    float4 ze = zr[threadIdx.x];
    float4 cq = cr[threadIdx.x];
    float d0 = cq.x - ze.x, d1 = cq.y - ze.y, d2 = cq.z - ze.z, d3 = cq.w - ze.w;
    float4 o;
    o.x = ze.x + d0; o.y = ze.y + d1; o.z = ze.z + d2; o.w = ze.w + d3;
    qr[threadIdx.x] = o;
    float s = d0 * d0 + d1 * d1 + d2 * d2 + d3 * d3;
    #pragma unroll
    for (int off = 16; off; off >>= 1) s += __shfl_down_sync(0xffffffffu, s, off);
    __shared__ float ws[4];
    if ((threadIdx.x & 31) == 0) ws[threadIdx.x >> 5] = s;
    __syncthreads();
    if (threadIdx.x == 0) {
        g_partials[m] = ws[0] + ws[1] + ws[2] + ws[3];
        out_idx[m] = (float)idx;
    }
}

__global__ void loss_kernel(float* __restrict__ out_loss, int M, int K)
{
    __shared__ float sm[1024];
    float s = 0.f;
    for (int i = threadIdx.x; i < M; i += 1024) s += g_partials[i];
    sm[threadIdx.x] = s;
    __syncthreads();
    for (int o = 512; o; o >>= 1) {
        if (threadIdx.x < o) sm[threadIdx.x] += sm[threadIdx.x + o];
        __syncthreads();
    }
    if (threadIdx.x == 0) {
        float mean = sm[0] / ((float)M * (float)K);
        out_loss[0] = (mean + 0.25f * mean) / (float)K;
    }
}

// ------------------------------------------------------------ launch
extern "C" void kernel_launch(void* const* d_in, const int* in_sizes, int n_in,
                              void* d_out, int out_size)
{
    const float* z  = (const float*)d_in[0];
    const float* cb = (const float*)d_in[1];
    const int M = in_sizes[0] / KDIM;   // 32768
    const int N = in_sizes[1] / KDIM;   // 8192

    float* out      = (float*)d_out;
    float* out_q    = out;
    float* out_idx  = out + (size_t)M * KDIM;
    float* out_loss = out_idx + M;

    static int attr_done = 0;
    if (!attr_done) {
        cudaFuncSetAttribute(gemm_hmma_kernel,
                             cudaFuncAttributeMaxDynamicSharedMemorySize,
                             SMEM_DYN);
        attr_done = 1;
    }

    splitA_kernel<<<M * 128 / 256, 256>>>(z);
    splitB_kernel<<<N * 128 / 256, 256>>>(cb);

    dim3 grid(N / BN, M / BM);
    gemm_hmma_kernel<<<grid, 256, SMEM_DYN>>>();

    refine_kernel<<<M, 256>>>(z, cb);
    gather_loss_kernel<<<M, 128>>>(z, cb, out_q, out_idx);
    loss_kernel<<<1, 1024>>>(out_loss, M, KDIM);
}

// round 14
// speedup vs baseline: 2.1609x; 1.0118x over previous
#include <cuda_runtime.h>
#include <cuda_bf16.h>
#include <stdint.h>

// ----------------------------------------------------------------------------
// VQExpert, two-phase: (1) bf16 hi-only HMMA GEMM -> approximate distances,
// per-16-code-group best keys + per-row global min key (atomicMin);
// (2) refine: exact fp32 distance for codes in groups within DELTA of the
// row's best approx distance, fused with gather (z_q_st write) + loss partial.
// R14: refine loses its row-min scan (GEMM provides it) and absorbs the
// gather kernel (z row already staged in refine's smem).
// ----------------------------------------------------------------------------

#define KDIM 512
#define MDIM 32768
#define NDIM 8192
#define BM 128
#define BN 128
#define BK 32
#define STAGES 3
#define NKT (KDIM / BK)        // 16
#define NGRP (NDIM / 16)       // 512 groups of 16 codes
#define DELTA 0.10f
// stage regions: Ah 8KB | Bh 8KB ; stage = 16KB
#define R_BH 8192
#define STG  16384
#define SMEM_DYN (STAGES * STG)   // 49152

__device__ __align__(16) __nv_bfloat16 g_Ah[(size_t)MDIM * KDIM];
__device__ __align__(16) __nv_bfloat16 g_Bh[(size_t)NDIM * KDIM];
__device__ float g_zsq[MDIM];
__device__ float g_esq[NDIM];
__device__ unsigned long long g_gb[(size_t)MDIM * NGRP];  // per-row group keys
__device__ unsigned long long g_best[MDIM];               // per-row min key
__device__ float g_partials[MDIM];

// ------------------------------------------------------------ PTX helpers
__device__ __forceinline__ uint32_t smem_u32(const void* p) {
    uint32_t a;
    asm("{ .reg .u64 t; cvta.to.shared.u64 t, %1; cvt.u32.u64 %0, t; }"
        : "=r"(a) : "l"(p));
    return a;
}
__device__ __forceinline__ void cp16(uint32_t dst, const void* src) {
    asm volatile("cp.async.cg.shared.global [%0], [%1], 16;"
                 :: "r"(dst), "l"(src) : "memory");
}
__device__ __forceinline__ void ldsm4(uint32_t* r, uint32_t addr) {
    asm volatile("ldmatrix.sync.aligned.m8n8.x4.shared.b16 {%0,%1,%2,%3}, [%4];"
                 : "=r"(r[0]), "=r"(r[1]), "=r"(r[2]), "=r"(r[3]) : "r"(addr));
}
__device__ __forceinline__ void mma16816(float* c, const uint32_t* a,
                                         uint32_t b0, uint32_t b1) {
    asm volatile(
        "mma.sync.aligned.m16n8k16.row.col.f32.bf16.bf16.f32 "
        "{%0,%1,%2,%3}, {%4,%5,%6,%7}, {%8,%9}, {%0,%1,%2,%3};"
        : "+f"(c[0]), "+f"(c[1]), "+f"(c[2]), "+f"(c[3])
        : "r"(a[0]), "r"(a[1]), "r"(a[2]), "r"(a[3]), "r"(b0), "r"(b1));
}
__device__ __forceinline__ uint32_t swz64(uint32_t off) {
    return off ^ ((off >> 3) & 0x30);
}
__device__ __forceinline__ uint32_t packbf2(__nv_bfloat16 a, __nv_bfloat16 b) {
    __nv_bfloat162 t; t.x = a; t.y = b;
    return *(uint32_t*)&t;
}
__device__ __forceinline__ unsigned enc(float f) {
    unsigned u = __float_as_uint(f);
    return (u & 0x80000000u) ? ~u : (u | 0x80000000u);
}
__device__ __forceinline__ float dec(unsigned x) {
    return (x & 0x80000000u) ? __uint_as_float(x & 0x7FFFFFFFu)
                             : __uint_as_float(~x);
}

// ------------------------------------------------------------ split + sumsq
__global__ void splitA_kernel(const float* __restrict__ z)
{
    int i = blockIdx.x * 256 + threadIdx.x;     // over MDIM*128
    int m = i >> 7, kc = (i & 127) << 2;
    float4 v = *(const float4*)(z + (size_t)m * KDIM + kc);
    uint2 H;
    H.x = packbf2(__float2bfloat16(v.x), __float2bfloat16(v.y));
    H.y = packbf2(__float2bfloat16(v.z), __float2bfloat16(v.w));
    *(uint2*)(g_Ah + (size_t)m * KDIM + kc) = H;
    float s = v.x * v.x + v.y * v.y + v.z * v.z + v.w * v.w;
    #pragma unroll
    for (int o = 16; o; o >>= 1) s += __shfl_down_sync(0xffffffffu, s, o);
    __shared__ float ws[8];
    int t = threadIdx.x;
    if ((t & 31) == 0) ws[t >> 5] = s;
    __syncthreads();
    if (t == 0)   g_zsq[m] = ws[0] + ws[1] + ws[2] + ws[3];
    if (t == 128) g_zsq[m] = ws[4] + ws[5] + ws[6] + ws[7];
}
__global__ void splitB_kernel(const float* __restrict__ cb)
{
    int i = blockIdx.x * 256 + threadIdx.x;     // over NDIM*128
    int n = i >> 7, kc = (i & 127) << 2;
    float4 v = *(const float4*)(cb + (size_t)n * KDIM + kc);
    uint2 H;
    H.x = packbf2(__float2bfloat16(v.x), __float2bfloat16(v.y));
    H.y = packbf2(__float2bfloat16(v.z), __float2bfloat16(v.w));
    *(uint2*)(g_Bh + (size_t)n * KDIM + kc) = H;
    float s = v.x * v.x + v.y * v.y + v.z * v.z + v.w * v.w;
    #pragma unroll
    for (int o = 16; o; o >>= 1) s += __shfl_down_sync(0xffffffffu, s, o);
    __shared__ float ws[8];
    int t = threadIdx.x;
    if ((t & 31) == 0) ws[t >> 5] = s;
    __syncthreads();
    if (t == 0)   g_esq[n] = ws[0] + ws[1] + ws[2] + ws[3];
    if (t == 128) g_esq[n] = ws[4] + ws[5] + ws[6] + ws[7];
}

__global__ void init_best_kernel(int M)
{
    int i = blockIdx.x * blockDim.x + threadIdx.x;
    if (i < M) g_best[i] = 0xFFFFFFFFFFFFFFFFull;
}

// ------------------------------------------------------------ hi-only GEMM
__global__ __launch_bounds__(256, 2)
void gemm_hmma_kernel()
{
    extern __shared__ char smem[];
    __shared__ float s_esq[BN];
    const uint32_t smb = smem_u32(smem);
    const int tid = threadIdx.x;
    const int lane = tid & 31, warp = tid >> 5;
    const int m0 = blockIdx.y * BM;
    const int n0 = blockIdx.x * BN;

    uint32_t swo[2];
    const __nv_bfloat16 *sAh[2], *sBh[2];
    #pragma unroll
    for (int r = 0; r < 2; r++) {
        int q = tid + r * 256, row = q >> 2, c = q & 3;
        swo[r] = swz64(row * 64 + c * 16);
        sAh[r] = g_Ah + (size_t)(m0 + row) * KDIM + c * 8;
        sBh[r] = g_Bh + (size_t)(n0 + row) * KDIM + c * 8;
    }

    #pragma unroll
    for (int s = 0; s < STAGES - 1; s++) {
        uint32_t bo = (uint32_t)s * STG;
        int k0 = s * BK;
        #pragma unroll
        for (int r = 0; r < 2; r++) {
            cp16(smb + bo + swo[r],        sAh[r] + k0);
            cp16(smb + bo + R_BH + swo[r], sBh[r] + k0);
        }
        asm volatile("cp.async.commit_group;" ::: "memory");
    }

    if (tid < BN) s_esq[tid] = g_esq[n0 + tid];

    float acc[4][4][4];
    #pragma unroll
    for (int i = 0; i < 4; i++)
        #pragma unroll
        for (int j = 0; j < 4; j++)
            #pragma unroll
            for (int q = 0; q < 4; q++) acc[i][j][q] = 0.f;

    const int wm = (warp & 1) * 64;
    const int wn = (warp >> 1) * 32;
    const uint32_t a_row = wm + (lane & 15);
    const uint32_t b_row = wn + (lane & 15);
    const uint32_t kchunk = (lane >> 4);

    for (int kt = 0; kt < NKT; kt++) {
        asm volatile("cp.async.wait_group %0;" :: "n"(STAGES - 2));
        __syncthreads();

        int pf = kt + STAGES - 1;
        if (pf < NKT) {
            uint32_t bo = (uint32_t)(pf % STAGES) * STG;
            int k0 = pf * BK;
            #pragma unroll
            for (int r = 0; r < 2; r++) {
                cp16(smb + bo + swo[r],        sAh[r] + k0);
                cp16(smb + bo + R_BH + swo[r], sBh[r] + k0);
            }
        }
        asm volatile("cp.async.commit_group;" ::: "memory");

        const uint32_t sA = smb + (uint32_t)(kt % STAGES) * STG;
        #pragma unroll
        for (int kk = 0; kk < 2; kk++) {
            const uint32_t kof = (kk * 2 + kchunk) * 16;
            uint32_t aH[4][4], b[2][4];
            #pragma unroll
            for (int i = 0; i < 4; i++)
                ldsm4(aH[i], sA + swz64((a_row + i * 16) * 64 + kof));
            #pragma unroll
            for (int p = 0; p < 2; p++)
                ldsm4(b[p], sA + R_BH + swz64((b_row + p * 16) * 64 + kof));
            #pragma unroll
            for (int i = 0; i < 4; i++)
                #pragma unroll
                for (int j = 0; j < 4; j++) {
                    int p = j >> 1, h = j & 1;
                    mma16816(acc[i][j], aH[i], b[p][h], b[p][h + 2]);
                }
        }
    }

    // ---- epilogue: approx dist' = esq - 2*acc; group keys + per-row min.
    const int r0 = lane >> 2;
    const int gbase = (n0 >> 4) + (wn >> 4);
    #pragma unroll
    for (int i = 0; i < 4; i++) {
        int rowa = wm + i * 16 + r0;
        unsigned long long rm0 = 0xFFFFFFFFFFFFFFFFull;
        unsigned long long rm1 = 0xFFFFFFFFFFFFFFFFull;
        #pragma unroll
        for (int jp = 0; jp < 2; jp++) {
            unsigned long long bk0 = 0xFFFFFFFFFFFFFFFFull;
            unsigned long long bk1 = 0xFFFFFFFFFFFFFFFFull;
            #pragma unroll
            for (int jj = 0; jj < 2; jj++) {
                int j = jp * 2 + jj;
                int ncol = wn + j * 8 + 2 * (lane & 3);
                float e0 = s_esq[ncol], e1 = s_esq[ncol + 1];
                unsigned gn0 = (unsigned)(n0 + ncol), gn1 = gn0 + 1;
                float d; unsigned long long k;
                d = e0 - 2.0f * acc[i][j][0];
                k = ((unsigned long long)enc(d) << 32) | gn0; if (k < bk0) bk0 = k;
                d = e1 - 2.0f * acc[i][j][1];
                k = ((unsigned long long)enc(d) << 32) | gn1; if (k < bk0) bk0 = k;
                d = e0 - 2.0f * acc[i][j][2];
                k = ((unsigned long long)enc(d) << 32) | gn0; if (k < bk1) bk1 = k;
                d = e1 - 2.0f * acc[i][j][3];
                k = ((unsigned long long)enc(d) << 32) | gn1; if (k < bk1) bk1 = k;
            }
            #pragma unroll
            for (int o = 1; o <= 2; o <<= 1) {
                unsigned long long t0 = __shfl_xor_sync(0xffffffffu, bk0, o);
                unsigned long long t1 = __shfl_xor_sync(0xffffffffu, bk1, o);
                if (t0 < bk0) bk0 = t0;
                if (t1 < bk1) bk1 = t1;
            }
            if ((lane & 3) == 0) {
                g_gb[(size_t)(m0 + rowa) * NGRP + gbase + jp] = bk0;
                g_gb[(size_t)(m0 + rowa + 8) * NGRP + gbase + jp] = bk1;
                if (bk0 < rm0) rm0 = bk0;
                if (bk1 < rm1) rm1 = bk1;
            }
        }
        if ((lane & 3) == 0) {
            atomicMin(&g_best[m0 + rowa], rm0);
            atomicMin(&g_best[m0 + rowa + 8], rm1);
        }
    }
}

// ------------------------------------------------------------ refine + gather
// One block (256 threads) per row. Row min comes from g_best (GEMM atomics).
// After exact argmin, writes z_q_st + loss partial directly (z row in smem).
__global__ __launch_bounds__(256)
void refine_kernel(const float* __restrict__ z, const float* __restrict__ cb,
                   float* __restrict__ out_q, float* __restrict__ out_idx)
{
    const int row = blockIdx.x;
    const int tid = threadIdx.x;
    const int lane = tid & 31, wid = tid >> 5;
    const unsigned long long* keys = g_gb + (size_t)row * NGRP;

    __shared__ unsigned long long s_best;
    __shared__ int s_cnt;
    __shared__ short s_list[64];
    __shared__ float4 s_z[128];   // the 2KB z row
    __shared__ float ws[4];

    if (tid == 0) {
        s_best = 0xFFFFFFFFFFFFFFFFull;
        s_cnt = 0;
    }
    if (tid < 128)
        s_z[tid] = ((const float4*)(z + (size_t)row * KDIM))[tid];
    __syncthreads();

    // phase 1 (free): threshold from GEMM-produced row min
    float th = dec((unsigned)(g_best[row] >> 32)) + DELTA;

    // phase 2: flag groups within threshold
    #pragma unroll
    for (int r = 0; r < 2; r++) {
        int g = tid + r * 256;
        if (dec((unsigned)(keys[g] >> 32)) <= th) {
            int p = atomicAdd(&s_cnt, 1);
            if (p < 64) s_list[p] = (short)g;
        }
    }
    __syncthreads();
    int nf = s_cnt < 64 ? s_cnt : 64;

    // phase 3: exact fp32 distances; 8 warps x 2 codes = 16 codes per group,
    // 16 lanes per code, coalesced (k*16 + l16), 4-way ILP.
    float zs = g_zsq[row];
    const int sub = lane >> 4;
    const int l16 = lane & 15;
    unsigned long long best = 0xFFFFFFFFFFFFFFFFull;
    for (int f = 0; f < nf; f++) {
        int code = (int)s_list[f] * 16 + wid * 2 + sub;
        const float4* cr = (const float4*)(cb + (size_t)code * KDIM);
        float d0 = 0.f, d1 = 0.f, d2 = 0.f, d3 = 0.f;
        #pragma unroll
        for (int q = 0; q < 2; q++) {
            int i0 = (q * 4 + 0) * 16 + l16;
            int i1 = (q * 4 + 1) * 16 + l16;
            int i2 = (q * 4 + 2) * 16 + l16;
            int i3 = (q * 4 + 3) * 16 + l16;
            float4 a0 = s_z[i0], b0 = cr[i0];
            float4 a1 = s_z[i1], b1 = cr[i1];
            float4 a2 = s_z[i2], b2 = cr[i2];
            float4 a3 = s_z[i3], b3 = cr[i3];
            d0 += a0.x * b0.x + a0.y * b0.y + a0.z * b0.z + a0.w * b0.w;
            d1 += a1.x * b1.x + a1.y * b1.y + a1.z * b1.z + a1.w * b1.w;
            d2 += a2.x * b2.x + a2.y * b2.y + a2.z * b2.z + a2.w * b2.w;
            d3 += a3.x * b3.x + a3.y * b3.y + a3.z * b3.z + a3.w * b3.w;
        }
        float dot = (d0 + d1) + (d2 + d3);
        #pragma unroll
        for (int o = 1; o <= 8; o <<= 1)
            dot += __shfl_xor_sync(0xffffffffu, dot, o);
        float d = (zs + g_esq[code]) - 2.0f * dot;
        unsigned long long key =
            ((unsigned long long)enc(d) << 32) | (unsigned)code;
        if (key < best) best = key;
    }
    #pragma unroll
    for (int o = 16; o; o >>= 1) {
        unsigned long long t = __shfl_xor_sync(0xffffffffu, best, o);
        if (t < best) best = t;
    }
    if (lane == 0) atomicMin(&s_best, best);
    __syncthreads();

    // phase 4: fused gather (z_q_st) + loss partial
    unsigned idx = (unsigned)s_best;
    if (tid < 128) {
        float4 ze = s_z[tid];
        float4 cq = ((const float4*)(cb + (size_t)idx * KDIM))[tid];
        float d0 = cq.x - ze.x, d1 = cq.y - ze.y;
        float d2 = cq.z - ze.z, d3 = cq.w - ze.w;
        float4 o;
        o.x = ze.x + d0; o.y = ze.y + d1; o.z = ze.z + d2; o.w = ze.w + d3;
        ((float4*)(out_q + (size_t)row * KDIM))[tid] = o;
        float s = d0 * d0 + d1 * d1 + d2 * d2 + d3 * d3;
        #pragma unroll
        for (int off = 16; off; off >>= 1)
            s += __shfl_down_sync(0xffffffffu, s, off);
        if (lane == 0) ws[wid] = s;
    }
    __syncthreads();
    if (tid == 0) {
        g_partials[row] = ws[0] + ws[1] + ws[2] + ws[3];
        out_idx[row] = (float)idx;
    }
}

__global__ void loss_kernel(float* __restrict__ out_loss, int M, int K)
{
    __shared__ float sm[1024];
    float s = 0.f;
    for (int i = threadIdx.x; i < M; i += 1024) s += g_partials[i];
    sm[threadIdx.x] = s;
    __syncthreads();
    for (int o = 512; o; o >>= 1) {
        if (threadIdx.x < o) sm[threadIdx.x] += sm[threadIdx.x + o];
        __syncthreads();
    }
    if (threadIdx.x == 0) {
        float mean = sm[0] / ((float)M * (float)K);
        out_loss[0] = (mean + 0.25f * mean) / (float)K;
    }
}

// ------------------------------------------------------------ launch
extern "C" void kernel_launch(void* const* d_in, const int* in_sizes, int n_in,
                              void* d_out, int out_size)
{
    const float* z  = (const float*)d_in[0];
    const float* cb = (const float*)d_in[1];
    const int M = in_sizes[0] / KDIM;   // 32768
    const int N = in_sizes[1] / KDIM;   // 8192

    float* out      = (float*)d_out;
    float* out_q    = out;
    float* out_idx  = out + (size_t)M * KDIM;
    float* out_loss = out_idx + M;

    static int attr_done = 0;
    if (!attr_done) {
        cudaFuncSetAttribute(gemm_hmma_kernel,
                             cudaFuncAttributeMaxDynamicSharedMemorySize,
                             SMEM_DYN);
        attr_done = 1;
    }

    splitA_kernel<<<M * 128 / 256, 256>>>(z);
    splitB_kernel<<<N * 128 / 256, 256>>>(cb);
    init_best_kernel<<<(M + 255) / 256, 256>>>(M);

    dim3 grid(N / BN, M / BM);
    gemm_hmma_kernel<<<grid, 256, SMEM_DYN>>>();

    refine_kernel<<<M, 256>>>(z, cb, out_q, out_idx);
    loss_kernel<<<1, 1024>>>(out_loss, M, KDIM);
}